// round 1
// baseline (speedup 1.0000x reference)
#include <cuda_runtime.h>

#define CC 64
#define MAXB 64
#define BM 112
#define XS_STRIDE 66

// Scratch (device globals — no allocations allowed)
__device__ float g_sums[MAXB * CC];
__device__ __align__(16) float g_Wt[CC * CC];   // g_Wt[j*64 + k] = W1[k][j] * bn_scale[j]
__device__ float g_c[MAXB * CC];                // per-segment fused bias (h@W1_bot + b1, BN-folded)

typedef unsigned long long u64;

__device__ __forceinline__ u64 ffma2(u64 a, u64 b, u64 c) {
    u64 d;
    asm("fma.rn.f32x2 %0, %1, %2, %3;" : "=l"(d) : "l"(a), "l"(b), "l"(c));
    return d;
}

__global__ void k_zero(int n) {
    int i = blockIdx.x * blockDim.x + threadIdx.x;
    if (i < n) g_sums[i] = 0.f;
}

// Pass 1: segment sums. Column-parallel, coalesced, 4-deep MLP.
__global__ void k_segsum(const float* __restrict__ x, const int* __restrict__ o,
                         int N, int B) {
    __shared__ int so[MAXB];
    if (threadIdx.x < B) so[threadIdx.x] = o[threadIdx.x];
    __syncthreads();
    int c  = threadIdx.x & (CC - 1);
    int rg = threadIdx.x >> 6;              // 0..3
    int rpb = (N + gridDim.x - 1) / gridDim.x;
    int r0 = blockIdx.x * rpb;
    if (r0 >= N) return;
    int r1 = min(N, r0 + rpb);
    int s0 = 0; while (s0 < B - 1 && r0 >= so[s0]) s0++;
    int s1 = s0; while (s1 < B - 1 && (r1 - 1) >= so[s1]) s1++;
    if (s0 == s1) {
        // fast path: whole block inside one segment
        float a0 = 0.f, a1 = 0.f, a2 = 0.f, a3 = 0.f;
        int row = r0 + rg;
        for (; row + 12 < r1; row += 16) {
            a0 += x[(size_t)(row     ) * CC + c];
            a1 += x[(size_t)(row +  4) * CC + c];
            a2 += x[(size_t)(row +  8) * CC + c];
            a3 += x[(size_t)(row + 12) * CC + c];
        }
        for (; row < r1; row += 4) a0 += x[(size_t)row * CC + c];
        float t = (a0 + a1) + (a2 + a3);
        atomicAdd(&g_sums[s0 * CC + c], t);
    } else {
        int seg = s0; float acc = 0.f;
        for (int row = r0 + rg; row < r1; row += 4) {
            while (seg < B - 1 && row >= so[seg]) {
                if (acc != 0.f) atomicAdd(&g_sums[seg * CC + c], acc);
                acc = 0.f; seg++;
            }
            acc += x[(size_t)row * CC + c];
        }
        if (acc != 0.f) atomicAdd(&g_sums[seg * CC + c], acc);
    }
}

// Pass 2 (tiny): mean -> h = relu(mean@W2+b2) -> fold BN into W' and per-seg bias c.
__global__ void k_prep(const int* __restrict__ o, const float* __restrict__ W2,
                       const float* __restrict__ b2, const float* __restrict__ W1,
                       const float* __restrict__ b1, const float* __restrict__ gam,
                       const float* __restrict__ bet, const float* __restrict__ rmean,
                       const float* __restrict__ rvar, int B) {
    __shared__ float mean[MAXB * CC];
    __shared__ float h[MAXB * CC];
    __shared__ float ss[CC], st[CC];
    int tid = threadIdx.x;
    if (tid < CC) {
        float sv = gam[tid] * rsqrtf(rvar[tid] + 1e-5f);
        ss[tid] = sv;
        st[tid] = bet[tid] - rmean[tid] * sv;
    }
    for (int i = tid; i < B * CC; i += blockDim.x) {
        int b = i >> 6;
        int cnt = o[b] - (b ? o[b - 1] : 0);
        mean[i] = g_sums[i] / (float)cnt;
    }
    __syncthreads();
    for (int i = tid; i < B * CC; i += blockDim.x) {
        int b = i >> 6, j = i & 63;
        float acc = b2[j];
        #pragma unroll 8
        for (int k = 0; k < CC; k++) acc = fmaf(mean[b * CC + k], W2[k * CC + j], acc);
        h[i] = fmaxf(acc, 0.f);
    }
    __syncthreads();
    for (int i = tid; i < CC * CC; i += blockDim.x) {
        int j = i >> 6, k = i & 63;
        g_Wt[i] = W1[k * CC + j] * ss[j];     // transposed + BN-scaled
    }
    for (int i = tid; i < B * CC; i += blockDim.x) {
        int b = i >> 6, j = i & 63;
        float acc = b1[j];
        #pragma unroll 8
        for (int k = 0; k < CC; k++) acc = fmaf(h[b * CC + k], W1[(CC + k) * CC + j], acc);
        g_c[i] = acc * ss[j] + st[j];
    }
}

// Pass 3: out = relu(x @ W' + c[seg])  — N x 64 x 64 GEMM with FFMA2 packed over K.
__global__ __launch_bounds__(256, 2)
void k_main(const float* __restrict__ x, const int* __restrict__ o,
            float* __restrict__ out, int N, int B) {
    __shared__ __align__(16) float xs[BM * XS_STRIDE];   // 29568 B
    __shared__ u64 wtu[CC * 32];                          // 16384 B, XOR-swizzled
    __shared__ unsigned char segb[BM];
    int tid = threadIdx.x;
    int base = blockIdx.x * BM;

    // W tile: swizzle u64 index by (j & 31) for conflict-free strided-column reads
    const u64* gW = reinterpret_cast<const u64*>(g_Wt);
    for (int i = tid; i < CC * 32; i += 256) {
        int j = i >> 5, kp = i & 31;
        wtu[(j << 5) + (kp ^ (j & 31))] = gW[i];
    }
    // x tile: coalesced float4 loads, padded-stride SMEM rows
    for (int i = tid; i < BM * 16; i += 256) {
        int r = i >> 4, k4 = i & 15;
        int row = base + r;
        float4 v = make_float4(0.f, 0.f, 0.f, 0.f);
        if (row < N) v = *reinterpret_cast<const float4*>(x + (size_t)row * CC + (k4 << 2));
        float* p = &xs[r * XS_STRIDE + (k4 << 2)];
        *reinterpret_cast<float2*>(p)     = make_float2(v.x, v.y);
        *reinterpret_cast<float2*>(p + 2) = make_float2(v.z, v.w);
    }
    // per-row segment ids
    if (tid < BM) {
        int row = min(base + tid, N - 1);
        int s = 0;
        while (s < B - 1 && row >= __ldg(&o[s])) s++;
        segb[tid] = (unsigned char)s;
    }
    __syncthreads();

    int cg = tid & 15, rg = tid >> 4;
    int r0 = rg * 7;
    u64 acc[7][4];
    #pragma unroll
    for (int r = 0; r < 7; r++)
        #pragma unroll
        for (int i = 0; i < 4; i++) acc[r][i] = 0ull;

    int jb[4], jk[4];
    #pragma unroll
    for (int i = 0; i < 4; i++) { int j = cg + 16 * i; jb[i] = j << 5; jk[i] = j & 31; }

    #pragma unroll 8
    for (int kp = 0; kp < 32; kp++) {
        u64 wv[4];
        #pragma unroll
        for (int i = 0; i < 4; i++) wv[i] = wtu[jb[i] + (kp ^ jk[i])];
        u64 xv[7];
        #pragma unroll
        for (int r = 0; r < 7; r++)
            xv[r] = *reinterpret_cast<const u64*>(&xs[(r0 + r) * XS_STRIDE + (kp << 1)]);
        #pragma unroll
        for (int r = 0; r < 7; r++)
            #pragma unroll
            for (int i = 0; i < 4; i++)
                acc[r][i] = ffma2(xv[r], wv[i], acc[r][i]);
    }

    #pragma unroll
    for (int r = 0; r < 7; r++) {
        int row = base + r0 + r;
        if (row < N) {
            const float* cb = &g_c[(int)segb[r0 + r] * CC];
            #pragma unroll
            for (int i = 0; i < 4; i++) {
                union { u64 u; float2 f; } cv; cv.u = acc[r][i];
                int col = cg + 16 * i;
                float v = cv.f.x + cv.f.y + __ldg(&cb[col]);
                out[(size_t)row * CC + col] = fmaxf(v, 0.f);
            }
        }
    }
}

extern "C" void kernel_launch(void* const* d_in, const int* in_sizes, int n_in,
                              void* d_out, int out_size) {
    const float* x     = (const float*)d_in[0];
    const int*   o     = (const int*)  d_in[1];
    const float* W2    = (const float*)d_in[2];
    const float* b2    = (const float*)d_in[3];
    const float* W1    = (const float*)d_in[4];
    const float* b1    = (const float*)d_in[5];
    const float* gam   = (const float*)d_in[6];
    const float* bet   = (const float*)d_in[7];
    const float* rmean = (const float*)d_in[8];
    const float* rvar  = (const float*)d_in[9];
    float* out = (float*)d_out;

    int N = in_sizes[0] / CC;
    int B = in_sizes[1];

    k_zero<<<(B * CC + 255) / 256, 256>>>(B * CC);
    k_segsum<<<4096, 256>>>(x, o, N, B);
    k_prep<<<1, 1024>>>(o, W2, b2, W1, b1, gam, bet, rmean, rvar, B);
    k_main<<<(N + BM - 1) / BM, 256>>>(x, o, out, N, B);
}

// round 5
// speedup vs baseline: 1.9916x; 1.9916x over previous
#include <cuda_runtime.h>
#include <cuda_bf16.h>
#include <cstdint>

#define CC 64
#define MAXB 64

// ---------------- device scratch (no allocations allowed) ----------------
__device__ float g_sums[MAXB * CC];
__device__ __align__(16) float g_c[MAXB * CC];        // per-segment fused bias (BN folded)
__device__ __align__(16) uint32_t g_Wfrag[4096];      // B operand, fragment-ready: hi tiles 0-3, lo tiles 4-7

// ---------------- pass 0: zero sums ----------------
__global__ void k_zero(int n) {
    int i = blockIdx.x * blockDim.x + threadIdx.x;
    if (i < n) g_sums[i] = 0.f;
}

// ---------------- pass 1: segment sums (float4 + smem tree + few atomics) ----------------
__global__ void k_segsum(const float4* __restrict__ x4, const int* __restrict__ o,
                         int N, int Bseg) {
    __shared__ int so[MAXB];
    __shared__ float4 red[256];
    int t = threadIdx.x;
    if (t < Bseg) so[t] = o[t];
    __syncthreads();
    int c4 = t & 15, rg = t >> 4;
    int rpb = (N + gridDim.x - 1) / gridDim.x;
    int r0 = blockIdx.x * rpb;
    if (r0 >= N) return;
    int r1 = min(N, r0 + rpb);
    int s0 = 0; while (s0 < Bseg - 1 && r0 >= so[s0]) s0++;
    int s1 = s0; while (s1 < Bseg - 1 && (r1 - 1) >= so[s1]) s1++;
    if (s0 == s1) {
        float4 a0 = make_float4(0.f, 0.f, 0.f, 0.f);
        float4 a1 = make_float4(0.f, 0.f, 0.f, 0.f);
        int row = r0 + rg;
        for (; row + 16 < r1; row += 32) {
            float4 v0 = x4[(size_t)row * 16 + c4];
            float4 v1 = x4[(size_t)(row + 16) * 16 + c4];
            a0.x += v0.x; a0.y += v0.y; a0.z += v0.z; a0.w += v0.w;
            a1.x += v1.x; a1.y += v1.y; a1.z += v1.z; a1.w += v1.w;
        }
        for (; row < r1; row += 16) {
            float4 v = x4[(size_t)row * 16 + c4];
            a0.x += v.x; a0.y += v.y; a0.z += v.z; a0.w += v.w;
        }
        a0.x += a1.x; a0.y += a1.y; a0.z += a1.z; a0.w += a1.w;
        red[t] = a0;
        __syncthreads();
        #pragma unroll
        for (int s = 8; s >= 1; s >>= 1) {
            if (rg < s) {
                float4 b = red[t + 16 * s];
                float4 a = red[t];
                a.x += b.x; a.y += b.y; a.z += b.z; a.w += b.w;
                red[t] = a;
            }
            __syncthreads();
        }
        if (rg == 0) {
            float4 v = red[t];
            float* dst = &g_sums[s0 * CC + c4 * 4];
            atomicAdd(dst + 0, v.x); atomicAdd(dst + 1, v.y);
            atomicAdd(dst + 2, v.z); atomicAdd(dst + 3, v.w);
        }
    } else {
        int seg = s0;
        float4 a = make_float4(0.f, 0.f, 0.f, 0.f);
        for (int row = r0 + rg; row < r1; row += 16) {
            while (seg < Bseg - 1 && row >= so[seg]) {
                float* dst = &g_sums[seg * CC + c4 * 4];
                atomicAdd(dst + 0, a.x); atomicAdd(dst + 1, a.y);
                atomicAdd(dst + 2, a.z); atomicAdd(dst + 3, a.w);
                a = make_float4(0.f, 0.f, 0.f, 0.f);
                seg++;
            }
            float4 v = x4[(size_t)row * 16 + c4];
            a.x += v.x; a.y += v.y; a.z += v.z; a.w += v.w;
        }
        float* dst = &g_sums[seg * CC + c4 * 4];
        atomicAdd(dst + 0, a.x); atomicAdd(dst + 1, a.y);
        atomicAdd(dst + 2, a.z); atomicAdd(dst + 3, a.w);
    }
}

// ---------------- pass 2 (tiny): MLP on pooled means, fold BN, build B frag image ----------------
__global__ void k_prep(const int* __restrict__ o, const float* __restrict__ W2,
                       const float* __restrict__ b2, const float* __restrict__ W1,
                       const float* __restrict__ b1, const float* __restrict__ gam,
                       const float* __restrict__ bet, const float* __restrict__ rmean,
                       const float* __restrict__ rvar, int Bseg) {
    __shared__ float mean[MAXB * CC];
    __shared__ float h[MAXB * CC];
    __shared__ float ss[CC], st[CC];
    int tid = threadIdx.x;
    if (tid < CC) {
        float sv = gam[tid] * rsqrtf(rvar[tid] + 1e-5f);
        ss[tid] = sv;
        st[tid] = bet[tid] - rmean[tid] * sv;
    }
    for (int i = tid; i < Bseg * CC; i += blockDim.x) {
        int b = i >> 6;
        int cnt = o[b] - (b ? o[b - 1] : 0);
        mean[i] = g_sums[i] / (float)cnt;
    }
    __syncthreads();
    for (int i = tid; i < Bseg * CC; i += blockDim.x) {
        int b = i >> 6, j = i & 63;
        float acc = b2[j];
        #pragma unroll 8
        for (int k = 0; k < CC; k++) acc = fmaf(mean[b * CC + k], W2[k * CC + j], acc);
        h[i] = fmaxf(acc, 0.f);
    }
    __syncthreads();
    // per-segment fused bias: c = (h @ W1_bot + b1) * ss + st
    for (int i = tid; i < Bseg * CC; i += blockDim.x) {
        int b = i >> 6, j = i & 63;
        float acc = b1[j];
        #pragma unroll 8
        for (int k = 0; k < CC; k++) acc = fmaf(h[b * CC + k], W1[(CC + k) * CC + j], acc);
        g_c[i] = acc * ss[j] + st[j];
    }
    // B operand fragment image for mma.m16n8k16 row.col:
    // word index i = ((kts*8 + nt)*32 + lane)*2 + bslot
    // b0/b1 hold W'[k][n], k = (kts&3)*16 + (lane&3)*2 + bslot*8 (+0,+1), n = nt*8 + lane/4
    // kts<4 -> hi(W'), kts>=4 -> lo(W'),  W'[k][n] = W1[k*CC+n]*ss[n]
    for (int i = tid; i < 4096; i += blockDim.x) {
        int bslot = i & 1;
        int lane = (i >> 1) & 31;
        int nt = (i >> 6) & 7;
        int kts = i >> 9;
        int n = nt * 8 + (lane >> 2);
        int k2 = (kts & 3) * 16 + (lane & 3) * 2 + bslot * 8;
        float sv = ss[n];
        float w0 = W1[k2 * CC + n] * sv;
        float w1 = W1[(k2 + 1) * CC + n] * sv;
        __nv_bfloat162 hp = __floats2bfloat162_rn(w0, w1);
        if (kts >= 4) {
            float l0 = w0 - __bfloat162float(hp.x);
            float l1 = w1 - __bfloat162float(hp.y);
            hp = __floats2bfloat162_rn(l0, l1);
        }
        g_Wfrag[i] = *reinterpret_cast<uint32_t*>(&hp);
    }
}

// ---------------- HMMA helper ----------------
__device__ __forceinline__ void mma16816(float* c, const uint4& a, uint32_t b0, uint32_t b1) {
    asm volatile(
        "mma.sync.aligned.m16n8k16.row.col.f32.bf16.bf16.f32 "
        "{%0,%1,%2,%3}, {%4,%5,%6,%7}, {%8,%9}, {%0,%1,%2,%3};"
        : "+f"(c[0]), "+f"(c[1]), "+f"(c[2]), "+f"(c[3])
        : "r"(a.x), "r"(a.y), "r"(a.z), "r"(a.w), "r"(b0), "r"(b1));
}

// ---------------- pass 3: out = relu(x @ W' + c[seg]) via HMMA 3-term hi/lo split ----------------
__global__ __launch_bounds__(256)
void k_main(const float4* __restrict__ x4, const int* __restrict__ o,
            float* __restrict__ out, int N, int Bseg) {
    __shared__ uint32_t Aimg[8192];   // 32 KB, fragment-ready: chunk=(row16*8 + kts), 128 words/chunk
    __shared__ uint32_t Bimg[4096];   // 16 KB
    int tid = threadIdx.x;
    int base = blockIdx.x * 128;

    // copy B frag image (coalesced, 16 KB)
    {
        const uint4* src = reinterpret_cast<const uint4*>(g_Wfrag);
        uint4* dst = reinterpret_cast<uint4*>(Bimg);
        #pragma unroll
        for (int j = 0; j < 4; j++) dst[tid + 256 * j] = src[tid + 256 * j];
    }

    // load x coalesced, convert to hi/lo bf16 pairs, scatter into fragment layout
    #pragma unroll
    for (int j = 0; j < 8; j++) {
        int idx = tid + 256 * j;
        int row = idx >> 4, c4 = idx & 15;
        int grow = base + row;
        float4 v = make_float4(0.f, 0.f, 0.f, 0.f);
        if (grow < N) v = x4[(size_t)grow * 16 + c4];

        int g = row & 7;
        int slot = ((row >> 3) & 1) + (c4 & 2);      // slot_m + 2*khigh
        int lbase = g * 4 + ((c4 & 1) << 1);          // lane for delta=0; +1 for delta=1
        int kts = c4 >> 2;
        uint32_t hi_a = (uint32_t)((((row >> 4) * 8 + kts) * 32 + lbase) * 4 + slot);
        uint32_t lo_a = hi_a + 4 * 128;               // kts+4 chunk

        __nv_bfloat162 h0 = __floats2bfloat162_rn(v.x, v.y);
        __nv_bfloat162 h1 = __floats2bfloat162_rn(v.z, v.w);
        float r0x = v.x - __bfloat162float(h0.x);
        float r0y = v.y - __bfloat162float(h0.y);
        float r1x = v.z - __bfloat162float(h1.x);
        float r1y = v.w - __bfloat162float(h1.y);
        __nv_bfloat162 l0 = __floats2bfloat162_rn(r0x, r0y);
        __nv_bfloat162 l1 = __floats2bfloat162_rn(r1x, r1y);

        Aimg[hi_a]     = *reinterpret_cast<uint32_t*>(&h0);
        Aimg[hi_a + 4] = *reinterpret_cast<uint32_t*>(&h1);   // delta=1 -> lane+1 -> +4 words
        Aimg[lo_a]     = *reinterpret_cast<uint32_t*>(&l0);
        Aimg[lo_a + 4] = *reinterpret_cast<uint32_t*>(&l1);
    }
    __syncthreads();

    int lane = tid & 31, wid = tid >> 5;
    int wm = wid & 3;      // row group: rows wm*32 .. +31
    int wn = wid >> 2;     // col group: cols wn*32 .. +31

    float acc[2][4][4];
    #pragma unroll
    for (int mb = 0; mb < 2; mb++)
        #pragma unroll
        for (int nt = 0; nt < 4; nt++)
            #pragma unroll
            for (int q = 0; q < 4; q++) acc[mb][nt][q] = 0.f;

    #pragma unroll
    for (int kt = 0; kt < 4; kt++) {
        uint4 ah[2], al[2];
        #pragma unroll
        for (int mb = 0; mb < 2; mb++) {
            int ch = (wm * 2 + mb) * 8;
            ah[mb] = *reinterpret_cast<const uint4*>(&Aimg[(ch + kt) * 128 + lane * 4]);
            al[mb] = *reinterpret_cast<const uint4*>(&Aimg[(ch + 4 + kt) * 128 + lane * 4]);
        }
        #pragma unroll
        for (int nt = 0; nt < 4; nt++) {
            int n = wn * 4 + nt;
            uint2 bh = *reinterpret_cast<const uint2*>(&Bimg[((kt * 8 + n) * 32 + lane) * 2]);
            uint2 bl = *reinterpret_cast<const uint2*>(&Bimg[(((kt + 4) * 8 + n) * 32 + lane) * 2]);
            #pragma unroll
            for (int mb = 0; mb < 2; mb++) {
                mma16816(acc[mb][nt], ah[mb], bh.x, bh.y);   // hi*hi
                mma16816(acc[mb][nt], ah[mb], bl.x, bl.y);   // hi*lo
                mma16816(acc[mb][nt], al[mb], bh.x, bh.y);   // lo*hi
            }
        }
    }

    // epilogue: bias + relu, direct full-sector STG.64
    int g = lane >> 2, cpair = (lane & 3) * 2;
    #pragma unroll
    for (int mb = 0; mb < 2; mb++) {
        int r0 = base + wm * 32 + mb * 16 + g;
        int r1 = r0 + 8;
        int s0 = 0; while (s0 < Bseg - 1 && r0 >= __ldg(&o[s0])) s0++;
        int s1 = s0; while (s1 < Bseg - 1 && r1 >= __ldg(&o[s1])) s1++;
        #pragma unroll
        for (int nt = 0; nt < 4; nt++) {
            int col = wn * 32 + nt * 8 + cpair;
            float2 bia0 = __ldg(reinterpret_cast<const float2*>(&g_c[s0 * CC + col]));
            float2 bia1 = __ldg(reinterpret_cast<const float2*>(&g_c[s1 * CC + col]));
            if (r0 < N) {
                float2 v;
                v.x = fmaxf(acc[mb][nt][0] + bia0.x, 0.f);
                v.y = fmaxf(acc[mb][nt][1] + bia0.y, 0.f);
                *reinterpret_cast<float2*>(&out[(size_t)r0 * CC + col]) = v;
            }
            if (r1 < N) {
                float2 v;
                v.x = fmaxf(acc[mb][nt][2] + bia1.x, 0.f);
                v.y = fmaxf(acc[mb][nt][3] + bia1.y, 0.f);
                *reinterpret_cast<float2*>(&out[(size_t)r1 * CC + col]) = v;
            }
        }
    }
}

extern "C" void kernel_launch(void* const* d_in, const int* in_sizes, int n_in,
                              void* d_out, int out_size) {
    const float* x     = (const float*)d_in[0];
    const int*   o     = (const int*)  d_in[1];
    const float* W2    = (const float*)d_in[2];
    const float* b2    = (const float*)d_in[3];
    const float* W1    = (const float*)d_in[4];
    const float* b1    = (const float*)d_in[5];
    const float* gam   = (const float*)d_in[6];
    const float* bet   = (const float*)d_in[7];
    const float* rmean = (const float*)d_in[8];
    const float* rvar  = (const float*)d_in[9];
    float* out = (float*)d_out;

    int N = in_sizes[0] / CC;
    int B = in_sizes[1];

    k_zero<<<(B * CC + 255) / 256, 256>>>(B * CC);
    k_segsum<<<4096, 256>>>((const float4*)x, o, N, B);
    k_prep<<<1, 1024>>>(o, W2, b2, W1, b1, gam, bet, rmean, rvar, B);
    k_main<<<(N + 127) / 128, 256>>>((const float4*)x, o, out, N, B);
}

// round 6
// speedup vs baseline: 2.1207x; 1.0648x over previous
#include <cuda_runtime.h>
#include <cuda_bf16.h>
#include <cstdint>

#define CC 64
#define MAXB 64

// ---------------- device scratch (no allocations allowed) ----------------
__device__ float g_sums[MAXB * CC];
__device__ __align__(16) float g_c[MAXB * CC];        // per-segment fused bias (BN folded)
__device__ __align__(16) uint32_t g_Wfrag[4096];      // B operand, fragment-ready: hi tiles 0-3, lo tiles 4-7

__device__ __forceinline__ uint32_t smem_u32(const void* p) {
    uint32_t a;
    asm("{ .reg .u64 t; cvta.to.shared.u64 t, %1; cvt.u32.u64 %0, t; }" : "=r"(a) : "l"(p));
    return a;
}

// ---------------- pass 0: zero sums ----------------
__global__ void k_zero(int n) {
    int i = blockIdx.x * blockDim.x + threadIdx.x;
    if (i < n) g_sums[i] = 0.f;
}

// ---------------- pass 1: segment sums (float4, MLP=4, smem tree, few atomics) ----------------
__global__ void k_segsum(const float4* __restrict__ x4, const int* __restrict__ o,
                         int N, int Bseg) {
    __shared__ int so[MAXB];
    __shared__ float4 red[256];
    int t = threadIdx.x;
    if (t < Bseg) so[t] = o[t];
    __syncthreads();
    int c4 = t & 15, rg = t >> 4;
    int rpb = (N + gridDim.x - 1) / gridDim.x;
    int r0 = blockIdx.x * rpb;
    if (r0 >= N) return;
    int r1 = min(N, r0 + rpb);
    int s0 = 0; while (s0 < Bseg - 1 && r0 >= so[s0]) s0++;
    int s1 = s0; while (s1 < Bseg - 1 && (r1 - 1) >= so[s1]) s1++;
    if (s0 == s1) {
        float4 a0 = make_float4(0.f, 0.f, 0.f, 0.f);
        float4 a1 = make_float4(0.f, 0.f, 0.f, 0.f);
        float4 a2 = make_float4(0.f, 0.f, 0.f, 0.f);
        float4 a3 = make_float4(0.f, 0.f, 0.f, 0.f);
        int row = r0 + rg;
        for (; row + 48 < r1; row += 64) {
            float4 v0 = x4[(size_t)row * 16 + c4];
            float4 v1 = x4[(size_t)(row + 16) * 16 + c4];
            float4 v2 = x4[(size_t)(row + 32) * 16 + c4];
            float4 v3 = x4[(size_t)(row + 48) * 16 + c4];
            a0.x += v0.x; a0.y += v0.y; a0.z += v0.z; a0.w += v0.w;
            a1.x += v1.x; a1.y += v1.y; a1.z += v1.z; a1.w += v1.w;
            a2.x += v2.x; a2.y += v2.y; a2.z += v2.z; a2.w += v2.w;
            a3.x += v3.x; a3.y += v3.y; a3.z += v3.z; a3.w += v3.w;
        }
        for (; row < r1; row += 16) {
            float4 v = x4[(size_t)row * 16 + c4];
            a0.x += v.x; a0.y += v.y; a0.z += v.z; a0.w += v.w;
        }
        a0.x += a1.x + a2.x + a3.x; a0.y += a1.y + a2.y + a3.y;
        a0.z += a1.z + a2.z + a3.z; a0.w += a1.w + a2.w + a3.w;
        red[t] = a0;
        __syncthreads();
        #pragma unroll
        for (int s = 8; s >= 1; s >>= 1) {
            if (rg < s) {
                float4 b = red[t + 16 * s];
                float4 a = red[t];
                a.x += b.x; a.y += b.y; a.z += b.z; a.w += b.w;
                red[t] = a;
            }
            __syncthreads();
        }
        if (rg == 0) {
            float4 v = red[t];
            float* dst = &g_sums[s0 * CC + c4 * 4];
            atomicAdd(dst + 0, v.x); atomicAdd(dst + 1, v.y);
            atomicAdd(dst + 2, v.z); atomicAdd(dst + 3, v.w);
        }
    } else {
        int seg = s0;
        float4 a = make_float4(0.f, 0.f, 0.f, 0.f);
        for (int row = r0 + rg; row < r1; row += 16) {
            while (seg < Bseg - 1 && row >= so[seg]) {
                float* dst = &g_sums[seg * CC + c4 * 4];
                atomicAdd(dst + 0, a.x); atomicAdd(dst + 1, a.y);
                atomicAdd(dst + 2, a.z); atomicAdd(dst + 3, a.w);
                a = make_float4(0.f, 0.f, 0.f, 0.f);
                seg++;
            }
            float4 v = x4[(size_t)row * 16 + c4];
            a.x += v.x; a.y += v.y; a.z += v.z; a.w += v.w;
        }
        float* dst = &g_sums[seg * CC + c4 * 4];
        atomicAdd(dst + 0, a.x); atomicAdd(dst + 1, a.y);
        atomicAdd(dst + 2, a.z); atomicAdd(dst + 3, a.w);
    }
}

// ---------------- pass 2 (tiny): MLP on pooled means, fold BN, build B frag image ----------------
__global__ void k_prep(const int* __restrict__ o, const float* __restrict__ W2,
                       const float* __restrict__ b2, const float* __restrict__ W1,
                       const float* __restrict__ b1, const float* __restrict__ gam,
                       const float* __restrict__ bet, const float* __restrict__ rmean,
                       const float* __restrict__ rvar, int Bseg) {
    __shared__ float mean[MAXB * CC];
    __shared__ float h[MAXB * CC];
    __shared__ float ss[CC], st[CC];
    int tid = threadIdx.x;
    if (tid < CC) {
        float sv = gam[tid] * rsqrtf(rvar[tid] + 1e-5f);
        ss[tid] = sv;
        st[tid] = bet[tid] - rmean[tid] * sv;
    }
    for (int i = tid; i < Bseg * CC; i += blockDim.x) {
        int b = i >> 6;
        int cnt = o[b] - (b ? o[b - 1] : 0);
        mean[i] = g_sums[i] / (float)cnt;
    }
    __syncthreads();
    for (int i = tid; i < Bseg * CC; i += blockDim.x) {
        int b = i >> 6, j = i & 63;
        float acc = b2[j];
        #pragma unroll 8
        for (int k = 0; k < CC; k++) acc = fmaf(mean[b * CC + k], W2[k * CC + j], acc);
        h[i] = fmaxf(acc, 0.f);
    }
    __syncthreads();
    // per-segment fused bias: c = (h @ W1_bot + b1) * ss + st
    for (int i = tid; i < Bseg * CC; i += blockDim.x) {
        int b = i >> 6, j = i & 63;
        float acc = b1[j];
        #pragma unroll 8
        for (int k = 0; k < CC; k++) acc = fmaf(h[b * CC + k], W1[(CC + k) * CC + j], acc);
        g_c[i] = acc * ss[j] + st[j];
    }
    // B operand fragment image for mma.m16n8k16 row.col:
    // word index i = ((kts*8 + nt)*32 + lane)*2 + bslot
    // b0/b1 hold W'[k][n], k = (kts&3)*16 + (lane&3)*2 + bslot*8 (+0,+1), n = nt*8 + lane/4
    // kts<4 -> hi(W'), kts>=4 -> lo(W'),  W'[k][n] = W1[k*CC+n]*ss[n]
    for (int i = tid; i < 4096; i += blockDim.x) {
        int bslot = i & 1;
        int lane = (i >> 1) & 31;
        int nt = (i >> 6) & 7;
        int kts = i >> 9;
        int n = nt * 8 + (lane >> 2);
        int k2 = (kts & 3) * 16 + (lane & 3) * 2 + bslot * 8;
        float sv = ss[n];
        float w0 = W1[k2 * CC + n] * sv;
        float w1 = W1[(k2 + 1) * CC + n] * sv;
        __nv_bfloat162 hp = __floats2bfloat162_rn(w0, w1);
        if (kts >= 4) {
            float l0 = w0 - __bfloat162float(hp.x);
            float l1 = w1 - __bfloat162float(hp.y);
            hp = __floats2bfloat162_rn(l0, l1);
        }
        g_Wfrag[i] = *reinterpret_cast<uint32_t*>(&hp);
    }
}

// ---------------- MMA / ldmatrix helpers ----------------
__device__ __forceinline__ void mma16816(float* c, const uint4& a, uint32_t b0, uint32_t b1) {
    asm volatile(
        "mma.sync.aligned.m16n8k16.row.col.f32.bf16.bf16.f32 "
        "{%0,%1,%2,%3}, {%4,%5,%6,%7}, {%8,%9}, {%0,%1,%2,%3};"
        : "+f"(c[0]), "+f"(c[1]), "+f"(c[2]), "+f"(c[3])
        : "r"(a.x), "r"(a.y), "r"(a.z), "r"(a.w), "r"(b0), "r"(b1));
}
__device__ __forceinline__ uint4 ldsm_x4(uint32_t addr) {
    uint4 r;
    asm volatile("ldmatrix.sync.aligned.m8n8.x4.shared.b16 {%0,%1,%2,%3}, [%4];"
        : "=r"(r.x), "=r"(r.y), "=r"(r.z), "=r"(r.w) : "r"(addr));
    return r;
}

// ---------------- pass 3: out = relu(x @ W' + c[seg]) via HMMA 3-term hi/lo split ----------------
// A panels: bf16[128 rows][64 k], 128 B/row, SW128 swizzle (byte ^= (row&7)<<4 on bits 4-6).
// hi panel at offset 0, lo panel at offset 16384.
struct __align__(1024) SmemM {
    unsigned char A[32768];
    uint32_t Bimg[4096];
};

__global__ __launch_bounds__(256)
void k_main(const float4* __restrict__ x4, const int* __restrict__ o,
            float* __restrict__ out, int N, int Bseg) {
    __shared__ SmemM sm;
    int tid = threadIdx.x;
    int base = blockIdx.x * 128;

    // copy B frag image (coalesced, 16 KB)
    {
        const uint4* src = reinterpret_cast<const uint4*>(g_Wfrag);
        uint4* dst = reinterpret_cast<uint4*>(sm.Bimg);
        #pragma unroll
        for (int j = 0; j < 4; j++) dst[tid + 256 * j] = src[tid + 256 * j];
    }

    // load x coalesced, convert hi/lo bf16, store row-major swizzled (2x STS.64/thread/iter)
    #pragma unroll
    for (int j = 0; j < 8; j++) {
        int idx = tid + 256 * j;
        int row = idx >> 4, c4 = idx & 15;
        int grow = base + row;
        float4 v = make_float4(0.f, 0.f, 0.f, 0.f);
        if (grow < N) v = x4[(size_t)grow * 16 + c4];

        __nv_bfloat162 h0 = __floats2bfloat162_rn(v.x, v.y);
        __nv_bfloat162 h1 = __floats2bfloat162_rn(v.z, v.w);
        float r0x = v.x - __bfloat162float(h0.x);
        float r0y = v.y - __bfloat162float(h0.y);
        float r1x = v.z - __bfloat162float(h1.x);
        float r1y = v.w - __bfloat162float(h1.y);
        __nv_bfloat162 l0 = __floats2bfloat162_rn(r0x, r0y);
        __nv_bfloat162 l1 = __floats2bfloat162_rn(r1x, r1y);

        uint32_t off = (uint32_t)(row * 128 + ((c4 * 8) ^ ((row & 7) << 4)));
        uint2 hw = make_uint2(*reinterpret_cast<uint32_t*>(&h0), *reinterpret_cast<uint32_t*>(&h1));
        uint2 lw = make_uint2(*reinterpret_cast<uint32_t*>(&l0), *reinterpret_cast<uint32_t*>(&l1));
        *reinterpret_cast<uint2*>(&sm.A[off])         = hw;
        *reinterpret_cast<uint2*>(&sm.A[off + 16384]) = lw;
    }
    __syncthreads();

    int lane = tid & 31, wid = tid >> 5;
    int wm = wid & 3;      // row group: rows wm*32 .. +31
    int wn = wid >> 2;     // col group: cols wn*32 .. +31

    // per-lane ldmatrix base: matrix m = lane>>3 -> (m&1): row+8, (m>>1): k+8
    int lm = lane >> 3, lr = lane & 7;
    uint32_t a_base = smem_u32(sm.A);
    // row component without mb: (wm*32 + (lm&1)*8 + lr) * 128 ; swizzled column base: ((lm>>1)*16) ^ (lr<<4)
    uint32_t lane_row = (uint32_t)(wm * 32 + (lm & 1) * 8 + lr) * 128u;

    float acc[2][4][4];
    #pragma unroll
    for (int mb = 0; mb < 2; mb++)
        #pragma unroll
        for (int nt = 0; nt < 4; nt++)
            #pragma unroll
            for (int q = 0; q < 4; q++) acc[mb][nt][q] = 0.f;

    #pragma unroll
    for (int kt = 0; kt < 4; kt++) {
        uint32_t kcol = (uint32_t)((kt * 32 + (lm >> 1) * 16) ^ (lr << 4));
        uint4 ah[2], al[2];
        #pragma unroll
        for (int mb = 0; mb < 2; mb++) {
            uint32_t addr = a_base + lane_row + (uint32_t)(mb * 16 * 128) + kcol;
            ah[mb] = ldsm_x4(addr);
            al[mb] = ldsm_x4(addr + 16384);
        }
        #pragma unroll
        for (int nt = 0; nt < 4; nt++) {
            int n = wn * 4 + nt;
            uint2 bh = *reinterpret_cast<const uint2*>(&sm.Bimg[((kt * 8 + n) * 32 + lane) * 2]);
            uint2 bl = *reinterpret_cast<const uint2*>(&sm.Bimg[(((kt + 4) * 8 + n) * 32 + lane) * 2]);
            #pragma unroll
            for (int mb = 0; mb < 2; mb++) {
                mma16816(acc[mb][nt], ah[mb], bh.x, bh.y);   // hi*hi
                mma16816(acc[mb][nt], ah[mb], bl.x, bl.y);   // hi*lo
                mma16816(acc[mb][nt], al[mb], bh.x, bh.y);   // lo*hi
            }
        }
    }

    // epilogue: bias + relu, direct full-sector STG.64
    int g = lane >> 2, cpair = (lane & 3) * 2;
    #pragma unroll
    for (int mb = 0; mb < 2; mb++) {
        int r0 = base + wm * 32 + mb * 16 + g;
        int r1 = r0 + 8;
        int s0 = 0; while (s0 < Bseg - 1 && r0 >= __ldg(&o[s0])) s0++;
        int s1 = s0; while (s1 < Bseg - 1 && r1 >= __ldg(&o[s1])) s1++;
        #pragma unroll
        for (int nt = 0; nt < 4; nt++) {
            int col = wn * 32 + nt * 8 + cpair;
            float2 bia0 = __ldg(reinterpret_cast<const float2*>(&g_c[s0 * CC + col]));
            float2 bia1 = __ldg(reinterpret_cast<const float2*>(&g_c[s1 * CC + col]));
            if (r0 < N) {
                float2 v;
                v.x = fmaxf(acc[mb][nt][0] + bia0.x, 0.f);
                v.y = fmaxf(acc[mb][nt][1] + bia0.y, 0.f);
                *reinterpret_cast<float2*>(&out[(size_t)r0 * CC + col]) = v;
            }
            if (r1 < N) {
                float2 v;
                v.x = fmaxf(acc[mb][nt][2] + bia1.x, 0.f);
                v.y = fmaxf(acc[mb][nt][3] + bia1.y, 0.f);
                *reinterpret_cast<float2*>(&out[(size_t)r1 * CC + col]) = v;
            }
        }
    }
}

extern "C" void kernel_launch(void* const* d_in, const int* in_sizes, int n_in,
                              void* d_out, int out_size) {
    const float* x     = (const float*)d_in[0];
    const int*   o     = (const int*)  d_in[1];
    const float* W2    = (const float*)d_in[2];
    const float* b2    = (const float*)d_in[3];
    const float* W1    = (const float*)d_in[4];
    const float* b1    = (const float*)d_in[5];
    const float* gam   = (const float*)d_in[6];
    const float* bet   = (const float*)d_in[7];
    const float* rmean = (const float*)d_in[8];
    const float* rvar  = (const float*)d_in[9];
    float* out = (float*)d_out;

    int N = in_sizes[0] / CC;
    int B = in_sizes[1];

    k_zero<<<(B * CC + 255) / 256, 256>>>(B * CC);
    k_segsum<<<4096, 256>>>((const float4*)x, o, N, B);
    k_prep<<<1, 1024>>>(o, W2, b2, W1, b1, gam, bet, rmean, rvar, B);
    k_main<<<(N + 127) / 128, 256>>>((const float4*)x, o, out, N, B);
}